// round 5
// baseline (speedup 1.0000x reference)
#include <cuda_runtime.h>
#include <math.h>
#include <stdint.h>

#define BTOT 8192
#define DDIM 256
#define MTILE 64
#define NTILE 64
#define NT (BTOT / NTILE)   // 128 n-tiles

// ---------------- static device scratch ----------------
__device__ float g_rnorm[BTOT];
__device__ float g_rowsum[BTOT];
__device__ float g_weighted[BTOT * DDIM];
__device__ float g_h[BTOT * DDIM];
__device__ float g_tf32[BTOT * DDIM];   // nodes rounded to tf32 (rna)

// ---------------- helpers ----------------
__device__ __forceinline__ float cvt_tf32(float x) {
    uint32_t o;
    asm volatile("cvt.rna.tf32.f32 %0, %1;" : "=r"(o) : "f"(x));
    return __uint_as_float(o);
}

__device__ __forceinline__ void mma8(float* c, const float* a, const float* b) {
    asm volatile(
        "mma.sync.aligned.m16n8k8.row.col.f32.tf32.tf32.f32 "
        "{%0,%1,%2,%3}, {%4,%5,%6,%7}, {%8,%9}, {%0,%1,%2,%3};\n"
        : "+f"(c[0]), "+f"(c[1]), "+f"(c[2]), "+f"(c[3])
        : "r"(__float_as_uint(a[0])), "r"(__float_as_uint(a[1])),
          "r"(__float_as_uint(a[2])), "r"(__float_as_uint(a[3])),
          "r"(__float_as_uint(b[0])), "r"(__float_as_uint(b[1])));
}

__device__ __forceinline__ uint32_t smem_u32(const void* p) {
    return (uint32_t)__cvta_generic_to_shared(p);
}

__device__ __forceinline__ void cp_async16(uint32_t dst, const void* src) {
    asm volatile("cp.async.cg.shared.global [%0], [%1], 16;\n" :: "r"(dst), "l"(src));
}
__device__ __forceinline__ void cp_commit() { asm volatile("cp.async.commit_group;\n"); }
__device__ __forceinline__ void cp_wait0()  { asm volatile("cp.async.wait_group 0;\n" ::: "memory"); }

// ---------------- K0: rnorm + tf32 conversion ----------------
__global__ void k_rnorm(const float* __restrict__ nodes) {
    int warp = (blockIdx.x * blockDim.x + threadIdx.x) >> 5;
    int lane = threadIdx.x & 31;
    if (warp >= BTOT) return;
    const float4* row = reinterpret_cast<const float4*>(nodes + (size_t)warp * DDIM);
    float4* trow = reinterpret_cast<float4*>(g_tf32 + (size_t)warp * DDIM);
    float ss = 0.f;
#pragma unroll
    for (int i = 0; i < 2; i++) {
        float4 v = row[lane + i * 32];
        ss += v.x * v.x + v.y * v.y + v.z * v.z + v.w * v.w;
        float4 t;
        t.x = cvt_tf32(v.x); t.y = cvt_tf32(v.y);
        t.z = cvt_tf32(v.z); t.w = cvt_tf32(v.w);
        trow[lane + i * 32] = t;
    }
#pragma unroll
    for (int o = 16; o > 0; o >>= 1) ss += __shfl_xor_sync(0xffffffffu, ss, o);
    if (lane == 0) {
        float nrm = fmaxf(sqrtf(ss), 1e-12f);
        g_rnorm[warp] = 1.0f / nrm;
    }
}

// ---------------- K1: fused sim->sigmoid/mask->rowsum + adj@nodes via tf32 mma ----------------
// 512 threads, 16 warps in a 4(m) x 4(n) grid.
#define QS_LD   260
#define KV_LD   260
#define PS_LD   68
#define SM_Q    0
#define SM_KV   (SM_Q + 64 * QS_LD)
#define SM_P    (SM_KV + 2 * 64 * KV_LD)
#define SM_RNK  (SM_P + 64 * PS_LD)
#define SM_PATK (SM_RNK + 2 * 64)
#define SM_INVR (SM_PATK + 2 * 64)
#define SM_RSP  (SM_INVR + 64)
#define SM_TOTAL ((SM_RSP + 4 * 64) * 4)

__global__ __launch_bounds__(512, 1)
void k_fused_mma(const int* __restrict__ pat,
                 const float* __restrict__ thrp,
                 const float* __restrict__ tmpp) {
    extern __shared__ float sm[];
    float* Qs   = sm + SM_Q;
    float* KV   = sm + SM_KV;
    float* Ps   = sm + SM_P;
    float* rnk  = sm + SM_RNK;
    int*   patk = (int*)(sm + SM_PATK);
    float* invr = sm + SM_INVR;
    float* rsp  = sm + SM_RSP;

    const int tid  = threadIdx.x;
    const int lane = tid & 31;
    const int wid  = tid >> 5;    // 0..15
    const int g    = lane >> 2;   // 0..7
    const int q    = lane & 3;    // 0..3
    const int wm   = wid & 3;     // m quadrant (16 rows)
    const int wn   = wid >> 2;    // 0..3
    const int m0   = blockIdx.x * MTILE;

    const int r0l = wm * 16 + g;  // local row of c0/c1
    const int r1l = r0l + 8;      // local row of c2/c3

    const float th   = fminf(fmaxf(thrp[0], 0.0f), 0.99f);
    const float temp = tmpp[0];

    const float rq0 = g_rnorm[m0 + r0l];
    const float rq1 = g_rnorm[m0 + r1l];
    const int   pq0 = pat[m0 + r0l];
    const int   pq1 = pat[m0 + r1l];

    // ---- prologue: cp.async Q tile + KV tile 0 ----
    {
        const float* qsrc = g_tf32 + (size_t)m0 * DDIM;
        uint32_t qdst = smem_u32(Qs);
        const float* ksrc = g_tf32;  // tile 0 base
        uint32_t kdst = smem_u32(KV);
#pragma unroll
        for (int i = 0; i < 8; i++) {
            int idx = tid + i * 512;           // 0..4095 float4 slots
            int r = idx >> 6, c4 = idx & 63;
            cp_async16(qdst + (uint32_t)(r * QS_LD + c4 * 4) * 4, qsrc + r * DDIM + c4 * 4);
            cp_async16(kdst + (uint32_t)(r * KV_LD + c4 * 4) * 4, ksrc + r * DDIM + c4 * 4);
        }
        cp_commit();
        if (tid < 64) {
            patk[tid] = pat[tid];
            rnk[tid]  = g_rnorm[tid];
        }
    }

    float oacc[8][4];
#pragma unroll
    for (int f = 0; f < 8; f++)
#pragma unroll
        for (int e = 0; e < 4; e++) oacc[f][e] = 0.f;
    float rs0 = 0.f, rs1 = 0.f;

    for (int jt = 0; jt < NT; jt++) {
        const int buf = jt & 1;
        const int n0  = jt * NTILE;

        cp_wait0();
        __syncthreads();

        // prefetch next tile into other buffer
        if (jt + 1 < NT) {
            const float* ksrc = g_tf32 + (size_t)(jt + 1) * NTILE * DDIM;
            uint32_t kdst = smem_u32(KV + (buf ^ 1) * 64 * KV_LD);
#pragma unroll
            for (int i = 0; i < 8; i++) {
                int idx = tid + i * 512;
                int r = idx >> 6, c4 = idx & 63;
                cp_async16(kdst + (uint32_t)(r * KV_LD + c4 * 4) * 4, ksrc + r * DDIM + c4 * 4);
            }
            cp_commit();
            if (tid < 64) {
                patk[(buf ^ 1) * 64 + tid] = pat[(jt + 1) * NTILE + tid];
                rnk[(buf ^ 1) * 64 + tid]  = g_rnorm[(jt + 1) * NTILE + tid];
            }
        }

        const float* kvb = KV + buf * 64 * KV_LD;

        // ---- S = Q · K^T : warp covers 16m x 16n ----
        float sacc[2][4];
#pragma unroll
        for (int f = 0; f < 2; f++)
#pragma unroll
            for (int e = 0; e < 4; e++) sacc[f][e] = 0.f;

        const float* qb0 = Qs + r0l * QS_LD;
        const float* qb1 = Qs + r1l * QS_LD;
#pragma unroll 8
        for (int ks = 0; ks < 32; ks++) {
            const int k0 = ks * 8 + q;
            float a[4] = { qb0[k0], qb1[k0], qb0[k0 + 4], qb1[k0 + 4] };
            const float* kb = kvb + (wn * 16 + g) * KV_LD + k0;
#pragma unroll
            for (int f = 0; f < 2; f++) {
                float b[2] = { kb[f * 8 * KV_LD], kb[f * 8 * KV_LD + 4] };
                mma8(sacc[f], a, b);
            }
        }

        // ---- sigmoid + mask -> P smem + rowsum partials ----
        const int gm0 = m0 + r0l;
        const int gm1 = m0 + r1l;
#pragma unroll
        for (int f = 0; f < 2; f++) {
            const int ln0 = wn * 16 + f * 8 + 2 * q;
            const int ln1 = ln0 + 1;
            const float rk0 = rnk[buf * 64 + ln0];
            const float rk1 = rnk[buf * 64 + ln1];
            const int   pk0 = patk[buf * 64 + ln0];
            const int   pk1 = patk[buf * 64 + ln1];
            const int gn0 = n0 + ln0, gn1 = n0 + ln1;

            float p00 = __fdividef(1.0f, 1.0f + __expf((th - sacc[f][0] * rq0 * rk0) * temp));
            float p01 = __fdividef(1.0f, 1.0f + __expf((th - sacc[f][1] * rq0 * rk1) * temp));
            float p10 = __fdividef(1.0f, 1.0f + __expf((th - sacc[f][2] * rq1 * rk0) * temp));
            float p11 = __fdividef(1.0f, 1.0f + __expf((th - sacc[f][3] * rq1 * rk1) * temp));
            if (gm0 == gn0 || pq0 == pk0) p00 = 0.f;
            if (gm0 == gn1 || pq0 == pk1) p01 = 0.f;
            if (gm1 == gn0 || pq1 == pk0) p10 = 0.f;
            if (gm1 == gn1 || pq1 == pk1) p11 = 0.f;
            rs0 += p00 + p01;
            rs1 += p10 + p11;
            *reinterpret_cast<float2*>(&Ps[r0l * PS_LD + ln0]) = make_float2(p00, p01);
            *reinterpret_cast<float2*>(&Ps[r1l * PS_LD + ln0]) = make_float2(p10, p11);
        }
        __syncthreads();

        // ---- O += P · V : warp covers 16m x 64d ----
        const float* pb0 = Ps + r0l * PS_LD;
        const float* pb1 = Ps + r1l * PS_LD;
#pragma unroll
        for (int ks = 0; ks < 8; ks++) {
            const int k0 = ks * 8 + q;
            float a[4] = { pb0[k0], pb1[k0], pb0[k0 + 4], pb1[k0 + 4] };
            const float* vb = kvb + k0 * KV_LD + wn * 64 + g;
#pragma unroll
            for (int f = 0; f < 8; f++) {
                float b[2] = { vb[f * 8], vb[f * 8 + 4 * KV_LD] };
                mma8(oacc[f], a, b);
            }
        }
    }

    // ---- rowsum reduce: over q lanes, then over the 4 n-warps ----
    rs0 += __shfl_xor_sync(0xffffffffu, rs0, 1);
    rs0 += __shfl_xor_sync(0xffffffffu, rs0, 2);
    rs1 += __shfl_xor_sync(0xffffffffu, rs1, 1);
    rs1 += __shfl_xor_sync(0xffffffffu, rs1, 2);
    __syncthreads();
    if (q == 0) {
        rsp[wn * 64 + r0l] = rs0;
        rsp[wn * 64 + r1l] = rs1;
    }
    __syncthreads();
    if (tid < 64) {
        float rs = rsp[tid] + rsp[64 + tid] + rsp[128 + tid] + rsp[192 + tid] + 1e-6f;
        g_rowsum[m0 + tid] = rs;
        invr[tid] = 1.0f / rs;
    }
    __syncthreads();

    const float i0 = invr[r0l];
    const float i1 = invr[r1l];
#pragma unroll
    for (int f = 0; f < 8; f++) {
        const int d = wn * 64 + f * 8 + 2 * q;
        *reinterpret_cast<float2*>(&g_weighted[(size_t)(m0 + r0l) * DDIM + d]) =
            make_float2(oacc[f][0] * i0, oacc[f][1] * i0);
        *reinterpret_cast<float2*>(&g_weighted[(size_t)(m0 + r1l) * DDIM + d]) =
            make_float2(oacc[f][2] * i1, oacc[f][3] * i1);
    }
}

// ---------------- K2: h = relu(weighted @ W1 + b1) ----------------
__global__ __launch_bounds__(256)
void k_mlp1(const float* __restrict__ W1, const float* __restrict__ b1) {
    __shared__ float As[32][68];
    __shared__ float Bs[32][64];
    const int tid = threadIdx.x;
    const int m0 = blockIdx.x * 64;
    const int n0 = blockIdx.y * 64;
    const int ty = tid >> 4, tx = tid & 15;
    float acc[4][4];
#pragma unroll
    for (int i = 0; i < 4; i++)
#pragma unroll
        for (int j = 0; j < 4; j++) acc[i][j] = 0.f;

    for (int kk = 0; kk < DDIM; kk += 32) {
#pragma unroll
        for (int s = 0; s < 2; s++) {
            int idx = tid + s * 256;
            int m = idx >> 3, c4 = idx & 7;
            float4 v = *reinterpret_cast<const float4*>(&g_weighted[(size_t)(m0 + m) * DDIM + kk + c4 * 4]);
            int k = c4 * 4;
            As[k][m] = v.x; As[k + 1][m] = v.y; As[k + 2][m] = v.z; As[k + 3][m] = v.w;
        }
#pragma unroll
        for (int s = 0; s < 2; s++) {
            int idx = tid + s * 256;
            int kr = idx >> 4, c4 = idx & 15;
            float4 v = *reinterpret_cast<const float4*>(&W1[(size_t)(kk + kr) * 256 + n0 + c4 * 4]);
            *reinterpret_cast<float4*>(&Bs[kr][c4 * 4]) = v;
        }
        __syncthreads();
#pragma unroll
        for (int k = 0; k < 32; k++) {
            float4 a = *reinterpret_cast<const float4*>(&As[k][ty * 4]);
            float4 b = *reinterpret_cast<const float4*>(&Bs[k][tx * 4]);
            float av[4] = {a.x, a.y, a.z, a.w};
            float bv[4] = {b.x, b.y, b.z, b.w};
#pragma unroll
            for (int i = 0; i < 4; i++)
#pragma unroll
                for (int j = 0; j < 4; j++) acc[i][j] = fmaf(av[i], bv[j], acc[i][j]);
        }
        __syncthreads();
    }
    float bb[4];
#pragma unroll
    for (int j = 0; j < 4; j++) bb[j] = b1[n0 + tx * 4 + j];
#pragma unroll
    for (int i = 0; i < 4; i++) {
        int m = m0 + ty * 4 + i;
        float4 o;
        o.x = fmaxf(acc[i][0] + bb[0], 0.f);
        o.y = fmaxf(acc[i][1] + bb[1], 0.f);
        o.z = fmaxf(acc[i][2] + bb[2], 0.f);
        o.w = fmaxf(acc[i][3] + bb[3], 0.f);
        *reinterpret_cast<float4*>(&g_h[(size_t)m * DDIM + n0 + tx * 4]) = o;
    }
}

// ---------------- K3: film + gate + residual ----------------
__global__ __launch_bounds__(256)
void k_mlp2(const float* __restrict__ W2, const float* __restrict__ b2,
            const float* __restrict__ nodes, float* __restrict__ out) {
    __shared__ float As[32][68];
    __shared__ float B1s[32][64];
    __shared__ float B2s[32][64];
    const int tid = threadIdx.x;
    const int m0 = blockIdx.x * 64;
    const int c0 = blockIdx.y * 64;
    const int ty = tid >> 4, tx = tid & 15;
    float acc1[4][4], acc2[4][4];
#pragma unroll
    for (int i = 0; i < 4; i++)
#pragma unroll
        for (int j = 0; j < 4; j++) { acc1[i][j] = 0.f; acc2[i][j] = 0.f; }

    for (int kk = 0; kk < DDIM; kk += 32) {
#pragma unroll
        for (int s = 0; s < 2; s++) {
            int idx = tid + s * 256;
            int m = idx >> 3, c4 = idx & 7;
            float4 v = *reinterpret_cast<const float4*>(&g_h[(size_t)(m0 + m) * DDIM + kk + c4 * 4]);
            int k = c4 * 4;
            As[k][m] = v.x; As[k + 1][m] = v.y; As[k + 2][m] = v.z; As[k + 3][m] = v.w;
        }
#pragma unroll
        for (int s = 0; s < 2; s++) {
            int idx = tid + s * 256;
            int kr = idx >> 4, c4 = idx & 15;
            float4 v1 = *reinterpret_cast<const float4*>(&W2[(size_t)(kk + kr) * 512 + c0 + c4 * 4]);
            float4 v2 = *reinterpret_cast<const float4*>(&W2[(size_t)(kk + kr) * 512 + 256 + c0 + c4 * 4]);
            *reinterpret_cast<float4*>(&B1s[kr][c4 * 4]) = v1;
            *reinterpret_cast<float4*>(&B2s[kr][c4 * 4]) = v2;
        }
        __syncthreads();
#pragma unroll
        for (int k = 0; k < 32; k++) {
            float4 a  = *reinterpret_cast<const float4*>(&As[k][ty * 4]);
            float4 b1v = *reinterpret_cast<const float4*>(&B1s[k][tx * 4]);
            float4 b2v = *reinterpret_cast<const float4*>(&B2s[k][tx * 4]);
            float av[4] = {a.x, a.y, a.z, a.w};
            float bv1[4] = {b1v.x, b1v.y, b1v.z, b1v.w};
            float bv2[4] = {b2v.x, b2v.y, b2v.z, b2v.w};
#pragma unroll
            for (int i = 0; i < 4; i++)
#pragma unroll
                for (int j = 0; j < 4; j++) {
                    acc1[i][j] = fmaf(av[i], bv1[j], acc1[i][j]);
                    acc2[i][j] = fmaf(av[i], bv2[j], acc2[i][j]);
                }
        }
        __syncthreads();
    }

    float bg[4], bb[4];
#pragma unroll
    for (int j = 0; j < 4; j++) {
        bg[j] = b2[c0 + tx * 4 + j];
        bb[j] = b2[256 + c0 + tx * 4 + j];
    }
#pragma unroll
    for (int i = 0; i < 4; i++) {
        int m = m0 + ty * 4 + i;
        float gate = tanhf(g_rowsum[m]);
        float4 nd = *reinterpret_cast<const float4*>(&nodes[(size_t)m * DDIM + c0 + tx * 4]);
        float ndv[4] = {nd.x, nd.y, nd.z, nd.w};
        float4 o;
        float ov[4];
#pragma unroll
        for (int j = 0; j < 4; j++) {
            float gamma = acc1[i][j] + bg[j];
            float beta  = acc2[i][j] + bb[j];
            float film  = fmaf(1.0f + gamma, ndv[j], beta);
            ov[j] = fmaf(film, gate, ndv[j]);
        }
        o.x = ov[0]; o.y = ov[1]; o.z = ov[2]; o.w = ov[3];
        *reinterpret_cast<float4*>(&out[(size_t)m * DDIM + c0 + tx * 4]) = o;
    }
}

// ---------------- host launcher ----------------
extern "C" void kernel_launch(void* const* d_in, const int* in_sizes, int n_in,
                              void* d_out, int out_size) {
    const float* nodes = (const float*)d_in[0];
    const int*   pat   = (const int*)d_in[1];
    const float* thr   = (const float*)d_in[2];
    const float* tmp   = (const float*)d_in[3];
    const float* W1    = (const float*)d_in[4];
    const float* b1    = (const float*)d_in[5];
    const float* W2    = (const float*)d_in[6];
    const float* b2    = (const float*)d_in[7];
    float* out = (float*)d_out;

    (void)cudaFuncSetAttribute(k_fused_mma, cudaFuncAttributeMaxDynamicSharedMemorySize,
                               SM_TOTAL);

    k_rnorm<<<BTOT / 8, 256>>>(nodes);
    k_fused_mma<<<BTOT / MTILE, 512, SM_TOTAL>>>(pat, thr, tmp);
    dim3 g2(BTOT / 64, DDIM / 64);
    k_mlp1<<<g2, 256>>>(W1, b1);
    k_mlp2<<<g2, 256>>>(W2, b2, nodes, out);
}

// round 7
// speedup vs baseline: 1.2314x; 1.2314x over previous
#include <cuda_runtime.h>
#include <math.h>
#include <stdint.h>

#define BTOT 8192
#define DDIM 256
#define MTILE 64
#define NTILE 64
#define NT (BTOT / NTILE)   // 128 n-tiles

// ---------------- static device scratch ----------------
__device__ float    g_rnorm[BTOT];
__device__ float    g_rowsum[BTOT];
__device__ float    g_weighted[BTOT * DDIM];
__device__ float    g_h[BTOT * DDIM];
__device__ uint32_t g_qk[BTOT * (DDIM / 2)];   // nodes as packed bf16 pairs (along d)

// ---------------- helpers ----------------
__device__ __forceinline__ uint32_t pack_bf16(float hi, float lo) {
    uint32_t d;
    asm volatile("cvt.rn.bf16x2.f32 %0, %1, %2;" : "=r"(d) : "f"(hi), "f"(lo));
    return d;
}

// tf32 m16n8k8 (fp32 operands fed raw; HW uses tf32 precision)
__device__ __forceinline__ void mma8(float* c, const float* a, const float* b) {
    asm volatile(
        "mma.sync.aligned.m16n8k8.row.col.f32.tf32.tf32.f32 "
        "{%0,%1,%2,%3}, {%4,%5,%6,%7}, {%8,%9}, {%0,%1,%2,%3};\n"
        : "+f"(c[0]), "+f"(c[1]), "+f"(c[2]), "+f"(c[3])
        : "r"(__float_as_uint(a[0])), "r"(__float_as_uint(a[1])),
          "r"(__float_as_uint(a[2])), "r"(__float_as_uint(a[3])),
          "r"(__float_as_uint(b[0])), "r"(__float_as_uint(b[1])));
}

// bf16 m16n8k16
__device__ __forceinline__ void mma16bf(float* c, const uint32_t* a, uint32_t b0, uint32_t b1) {
    asm volatile(
        "mma.sync.aligned.m16n8k16.row.col.f32.bf16.bf16.f32 "
        "{%0,%1,%2,%3}, {%4,%5,%6,%7}, {%8,%9}, {%0,%1,%2,%3};\n"
        : "+f"(c[0]), "+f"(c[1]), "+f"(c[2]), "+f"(c[3])
        : "r"(a[0]), "r"(a[1]), "r"(a[2]), "r"(a[3]),
          "r"(b0), "r"(b1));
}

__device__ __forceinline__ uint32_t smem_u32(const void* p) {
    return (uint32_t)__cvta_generic_to_shared(p);
}
__device__ __forceinline__ void cp_async16(uint32_t dst, const void* src) {
    asm volatile("cp.async.cg.shared.global [%0], [%1], 16;\n" :: "r"(dst), "l"(src));
}
__device__ __forceinline__ void cp_commit() { asm volatile("cp.async.commit_group;\n"); }
__device__ __forceinline__ void cp_wait0()  { asm volatile("cp.async.wait_group 0;\n" ::: "memory"); }

// ---------------- K0: rnorm + bf16 pack ----------------
__global__ void k_rnorm(const float* __restrict__ nodes) {
    int warp = (blockIdx.x * blockDim.x + threadIdx.x) >> 5;
    int lane = threadIdx.x & 31;
    if (warp >= BTOT) return;
    const float4* row = reinterpret_cast<const float4*>(nodes + (size_t)warp * DDIM);
    uint2* qrow = reinterpret_cast<uint2*>(g_qk + (size_t)warp * (DDIM / 2));
    float ss = 0.f;
#pragma unroll
    for (int i = 0; i < 2; i++) {
        float4 v = row[lane + i * 32];
        ss += v.x * v.x + v.y * v.y + v.z * v.z + v.w * v.w;
        uint2 p;
        p.x = pack_bf16(v.y, v.x);  // word: hi = k odd, lo = k even
        p.y = pack_bf16(v.w, v.z);
        qrow[lane + i * 32] = p;
    }
#pragma unroll
    for (int o = 16; o > 0; o >>= 1) ss += __shfl_xor_sync(0xffffffffu, ss, o);
    if (lane == 0) {
        float nrm = fmaxf(sqrtf(ss), 1e-12f);
        g_rnorm[warp] = 1.0f / nrm;
    }
}

// ---------------- K1: fused adj pipeline ----------------
// 256 threads / 8 warps. S-grid: 4m x 2n (warp 16m x 32n, bf16 mma, Q in regs).
// O-grid: 2m x 4d (warp 32m x 64d, tf32 mma).
#define KB_LD 132    // u32 per K-row (128 pairs + pad4)
#define V_LD  260    // f32 per V-row (256 + pad4)
#define PS_LD 68

#define SM_KB   0
#define SM_V    (SM_KB + 2 * 64 * KB_LD)            // u32 units
#define SM_P    (SM_V + 2 * 64 * V_LD)
#define SM_RNK  (SM_P + 64 * PS_LD)
#define SM_PATK (SM_RNK + 2 * 64)
#define SM_INVR (SM_PATK + 2 * 64)
#define SM_RSP  (SM_INVR + 64)
#define SM_TOTAL_BYTES ((SM_RSP + 2 * 64) * 4)

__global__ __launch_bounds__(256, 1)
void k_fused(const float* __restrict__ nodes,
             const int* __restrict__ pat,
             const float* __restrict__ thrp,
             const float* __restrict__ tmpp) {
    extern __shared__ uint32_t smu[];
    uint32_t* KB   = smu + SM_KB;
    float*    Vb   = reinterpret_cast<float*>(smu + SM_V);
    float*    Ps   = reinterpret_cast<float*>(smu + SM_P);
    float*    rnk  = reinterpret_cast<float*>(smu + SM_RNK);
    int*      patk = reinterpret_cast<int*>(smu + SM_PATK);
    float*    invr = reinterpret_cast<float*>(smu + SM_INVR);
    float*    rsp  = reinterpret_cast<float*>(smu + SM_RSP);

    const int tid  = threadIdx.x;
    const int lane = tid & 31;
    const int wid  = tid >> 5;
    const int g    = lane >> 2;
    const int q    = lane & 3;
    const int wm   = wid & 3;     // S-grid m quadrant
    const int wn   = wid >> 2;    // S-grid n half (0..1)
    const int wm2  = wid & 1;     // O-grid m half
    const int wd   = wid >> 1;    // O-grid d quarter (0..3)
    const int m0   = blockIdx.x * MTILE;

    const int r0l = wm * 16 + g;  // S rows
    const int r1l = r0l + 8;

    const float th   = fminf(fmaxf(thrp[0], 0.0f), 0.99f);
    const float temp = tmpp[0];

    const float rq0 = g_rnorm[m0 + r0l];
    const float rq1 = g_rnorm[m0 + r1l];
    const int   pq0 = pat[m0 + r0l];
    const int   pq1 = pat[m0 + r1l];

    // ---- prologue: issue K0/V0, then pull Q fragments into registers ----
    {
        const uint32_t* ksrc = g_qk;                 // tile 0
        uint32_t kdst = smem_u32(KB);
#pragma unroll
        for (int i = 0; i < 8; i++) {
            int idx = tid + i * 256;      // 2048 chunks of 16B
            int r = idx >> 5, c = idx & 31;
            cp_async16(kdst + (uint32_t)(r * KB_LD + c * 4) * 4, ksrc + r * (DDIM / 2) + c * 4);
        }
        const float* vsrc = nodes;                   // tile 0
        uint32_t vdst = smem_u32(Vb);
#pragma unroll
        for (int i = 0; i < 16; i++) {
            int idx = tid + i * 256;      // 4096 chunks of 16B
            int r = idx >> 6, c = idx & 63;
            cp_async16(vdst + (uint32_t)(r * V_LD + c * 4) * 4, vsrc + r * DDIM + c * 4);
        }
        cp_commit();
        if (tid < 64) {
            patk[tid] = pat[tid];
            rnk[tid]  = g_rnorm[tid];
        }
    }

    // Q fragments: 16 k-steps x 4 u32 (bf16 pairs)
    uint32_t qa[16][4];
    {
        const uint32_t* q0 = g_qk + (size_t)(m0 + r0l) * (DDIM / 2);
        const uint32_t* q1 = g_qk + (size_t)(m0 + r1l) * (DDIM / 2);
#pragma unroll
        for (int ks = 0; ks < 16; ks++) {
            qa[ks][0] = q0[ks * 8 + q];
            qa[ks][1] = q1[ks * 8 + q];
            qa[ks][2] = q0[ks * 8 + q + 4];
            qa[ks][3] = q1[ks * 8 + q + 4];
        }
    }

    float oacc[2][8][4];
#pragma unroll
    for (int mg = 0; mg < 2; mg++)
#pragma unroll
        for (int f = 0; f < 8; f++)
#pragma unroll
            for (int e = 0; e < 4; e++) oacc[mg][f][e] = 0.f;
    float rs0 = 0.f, rs1 = 0.f;

    for (int jt = 0; jt < NT; jt++) {
        const int buf = jt & 1;
        const int n0  = jt * NTILE;

        cp_wait0();
        __syncthreads();

        if (jt + 1 < NT) {
            const uint32_t* ksrc = g_qk + (size_t)(jt + 1) * NTILE * (DDIM / 2);
            uint32_t kdst = smem_u32(KB + (buf ^ 1) * 64 * KB_LD);
#pragma unroll
            for (int i = 0; i < 8; i++) {
                int idx = tid + i * 256;
                int r = idx >> 5, c = idx & 31;
                cp_async16(kdst + (uint32_t)(r * KB_LD + c * 4) * 4, ksrc + r * (DDIM / 2) + c * 4);
            }
            const float* vsrc = nodes + (size_t)(jt + 1) * NTILE * DDIM;
            uint32_t vdst = smem_u32(Vb + (buf ^ 1) * 64 * V_LD);
#pragma unroll
            for (int i = 0; i < 16; i++) {
                int idx = tid + i * 256;
                int r = idx >> 6, c = idx & 63;
                cp_async16(vdst + (uint32_t)(r * V_LD + c * 4) * 4, vsrc + r * DDIM + c * 4);
            }
            cp_commit();
            if (tid < 64) {
                patk[(buf ^ 1) * 64 + tid] = pat[(jt + 1) * NTILE + tid];
                rnk[(buf ^ 1) * 64 + tid]  = g_rnorm[(jt + 1) * NTILE + tid];
            }
        }

        const uint32_t* kb = KB + buf * 64 * KB_LD;

        // ---- S = Q (regs, bf16) x K^T (smem, bf16): warp 16m x 32n ----
        float sacc[4][4];
#pragma unroll
        for (int f = 0; f < 4; f++)
#pragma unroll
            for (int e = 0; e < 4; e++) sacc[f][e] = 0.f;

#pragma unroll 4
        for (int ks = 0; ks < 16; ks++) {
#pragma unroll
            for (int f = 0; f < 4; f++) {
                const uint32_t* kr = kb + (wn * 32 + f * 8 + g) * KB_LD + ks * 8 + q;
                mma16bf(sacc[f], qa[ks], kr[0], kr[4]);
            }
        }

        // ---- sigmoid + mask -> P (f32) + rowsum partials ----
        const int gm0 = m0 + r0l;
        const int gm1 = m0 + r1l;
#pragma unroll
        for (int f = 0; f < 4; f++) {
            const int ln0 = wn * 32 + f * 8 + 2 * q;
            const int ln1 = ln0 + 1;
            const float rk0 = rnk[buf * 64 + ln0];
            const float rk1 = rnk[buf * 64 + ln1];
            const int   pk0 = patk[buf * 64 + ln0];
            const int   pk1 = patk[buf * 64 + ln1];
            const int gn0 = n0 + ln0, gn1 = n0 + ln1;

            float p00 = __fdividef(1.0f, 1.0f + __expf((th - sacc[f][0] * rq0 * rk0) * temp));
            float p01 = __fdividef(1.0f, 1.0f + __expf((th - sacc[f][1] * rq0 * rk1) * temp));
            float p10 = __fdividef(1.0f, 1.0f + __expf((th - sacc[f][2] * rq1 * rk0) * temp));
            float p11 = __fdividef(1.0f, 1.0f + __expf((th - sacc[f][3] * rq1 * rk1) * temp));
            if (gm0 == gn0 || pq0 == pk0) p00 = 0.f;
            if (gm0 == gn1 || pq0 == pk1) p01 = 0.f;
            if (gm1 == gn0 || pq1 == pk0) p10 = 0.f;
            if (gm1 == gn1 || pq1 == pk1) p11 = 0.f;
            rs0 += p00 + p01;
            rs1 += p10 + p11;
            *reinterpret_cast<float2*>(&Ps[r0l * PS_LD + ln0]) = make_float2(p00, p01);
            *reinterpret_cast<float2*>(&Ps[r1l * PS_LD + ln0]) = make_float2(p10, p11);
        }
        __syncthreads();

        // ---- O += P x V (tf32): warp 32m x 64d ----
        const float* vt = Vb + buf * 64 * V_LD;
#pragma unroll
        for (int ks = 0; ks < 8; ks++) {
            const int k0 = ks * 8 + q;
            const float* vb = vt + k0 * V_LD + wd * 64 + g;
#pragma unroll
            for (int mg = 0; mg < 2; mg++) {
                const int rowb = wm2 * 32 + mg * 16;
                const float* pb0 = Ps + (rowb + g) * PS_LD;
                const float* pb1 = Ps + (rowb + g + 8) * PS_LD;
                float a[4] = { pb0[k0], pb1[k0], pb0[k0 + 4], pb1[k0 + 4] };
#pragma unroll
                for (int f = 0; f < 8; f++) {
                    float b[2] = { vb[f * 8], vb[f * 8 + 4 * V_LD] };
                    mma8(oacc[mg][f], a, b);
                }
            }
        }
    }

    // ---- rowsum reduce (quad lanes, then 2 n-warps) ----
    rs0 += __shfl_xor_sync(0xffffffffu, rs0, 1);
    rs0 += __shfl_xor_sync(0xffffffffu, rs0, 2);
    rs1 += __shfl_xor_sync(0xffffffffu, rs1, 1);
    rs1 += __shfl_xor_sync(0xffffffffu, rs1, 2);
    __syncthreads();
    if (q == 0) {
        rsp[wn * 64 + r0l] = rs0;
        rsp[wn * 64 + r1l] = rs1;
    }
    __syncthreads();
    if (tid < 64) {
        float rs = rsp[tid] + rsp[64 + tid] + 1e-6f;
        g_rowsum[m0 + tid] = rs;
        invr[tid] = 1.0f / rs;
    }
    __syncthreads();

    // ---- write normalized weighted neighbors ----
#pragma unroll
    for (int mg = 0; mg < 2; mg++) {
        const int row0 = wm2 * 32 + mg * 16 + g;
        const int row1 = row0 + 8;
        const float i0 = invr[row0];
        const float i1 = invr[row1];
#pragma unroll
        for (int f = 0; f < 8; f++) {
            const int d = wd * 64 + f * 8 + 2 * q;
            *reinterpret_cast<float2*>(&g_weighted[(size_t)(m0 + row0) * DDIM + d]) =
                make_float2(oacc[mg][f][0] * i0, oacc[mg][f][1] * i0);
            *reinterpret_cast<float2*>(&g_weighted[(size_t)(m0 + row1) * DDIM + d]) =
                make_float2(oacc[mg][f][2] * i1, oacc[mg][f][3] * i1);
        }
    }
}

// ---------------- K2: h = relu(weighted @ W1 + b1) ----------------
__global__ __launch_bounds__(256)
void k_mlp1(const float* __restrict__ W1, const float* __restrict__ b1) {
    __shared__ float As[32][68];
    __shared__ float Bs[32][64];
    const int tid = threadIdx.x;
    const int m0 = blockIdx.x * 64;
    const int n0 = blockIdx.y * 64;
    const int ty = tid >> 4, tx = tid & 15;
    float acc[4][4];
#pragma unroll
    for (int i = 0; i < 4; i++)
#pragma unroll
        for (int j = 0; j < 4; j++) acc[i][j] = 0.f;

    for (int kk = 0; kk < DDIM; kk += 32) {
#pragma unroll
        for (int s = 0; s < 2; s++) {
            int idx = tid + s * 256;
            int m = idx >> 3, c4 = idx & 7;
            float4 v = *reinterpret_cast<const float4*>(&g_weighted[(size_t)(m0 + m) * DDIM + kk + c4 * 4]);
            int k = c4 * 4;
            As[k][m] = v.x; As[k + 1][m] = v.y; As[k + 2][m] = v.z; As[k + 3][m] = v.w;
        }
#pragma unroll
        for (int s = 0; s < 2; s++) {
            int idx = tid + s * 256;
            int kr = idx >> 4, c4 = idx & 15;
            float4 v = *reinterpret_cast<const float4*>(&W1[(size_t)(kk + kr) * 256 + n0 + c4 * 4]);
            *reinterpret_cast<float4*>(&Bs[kr][c4 * 4]) = v;
        }
        __syncthreads();
#pragma unroll
        for (int k = 0; k < 32; k++) {
            float4 a = *reinterpret_cast<const float4*>(&As[k][ty * 4]);
            float4 b = *reinterpret_cast<const float4*>(&Bs[k][tx * 4]);
            float av[4] = {a.x, a.y, a.z, a.w};
            float bv[4] = {b.x, b.y, b.z, b.w};
#pragma unroll
            for (int i = 0; i < 4; i++)
#pragma unroll
                for (int j = 0; j < 4; j++) acc[i][j] = fmaf(av[i], bv[j], acc[i][j]);
        }
        __syncthreads();
    }
    float bb[4];
#pragma unroll
    for (int j = 0; j < 4; j++) bb[j] = b1[n0 + tx * 4 + j];
#pragma unroll
    for (int i = 0; i < 4; i++) {
        int m = m0 + ty * 4 + i;
        float4 o;
        o.x = fmaxf(acc[i][0] + bb[0], 0.f);
        o.y = fmaxf(acc[i][1] + bb[1], 0.f);
        o.z = fmaxf(acc[i][2] + bb[2], 0.f);
        o.w = fmaxf(acc[i][3] + bb[3], 0.f);
        *reinterpret_cast<float4*>(&g_h[(size_t)m * DDIM + n0 + tx * 4]) = o;
    }
}

// ---------------- K3: film + gate + residual ----------------
__global__ __launch_bounds__(256)
void k_mlp2(const float* __restrict__ W2, const float* __restrict__ b2,
            const float* __restrict__ nodes, float* __restrict__ out) {
    __shared__ float As[32][68];
    __shared__ float B1s[32][64];
    __shared__ float B2s[32][64];
    const int tid = threadIdx.x;
    const int m0 = blockIdx.x * 64;
    const int c0 = blockIdx.y * 64;
    const int ty = tid >> 4, tx = tid & 15;
    float acc1[4][4], acc2[4][4];
#pragma unroll
    for (int i = 0; i < 4; i++)
#pragma unroll
        for (int j = 0; j < 4; j++) { acc1[i][j] = 0.f; acc2[i][j] = 0.f; }

    for (int kk = 0; kk < DDIM; kk += 32) {
#pragma unroll
        for (int s = 0; s < 2; s++) {
            int idx = tid + s * 256;
            int m = idx >> 3, c4 = idx & 7;
            float4 v = *reinterpret_cast<const float4*>(&g_h[(size_t)(m0 + m) * DDIM + kk + c4 * 4]);
            int k = c4 * 4;
            As[k][m] = v.x; As[k + 1][m] = v.y; As[k + 2][m] = v.z; As[k + 3][m] = v.w;
        }
#pragma unroll
        for (int s = 0; s < 2; s++) {
            int idx = tid + s * 256;
            int kr = idx >> 4, c4 = idx & 15;
            float4 v1 = *reinterpret_cast<const float4*>(&W2[(size_t)(kk + kr) * 512 + c0 + c4 * 4]);
            float4 v2 = *reinterpret_cast<const float4*>(&W2[(size_t)(kk + kr) * 512 + 256 + c0 + c4 * 4]);
            *reinterpret_cast<float4*>(&B1s[kr][c4 * 4]) = v1;
            *reinterpret_cast<float4*>(&B2s[kr][c4 * 4]) = v2;
        }
        __syncthreads();
#pragma unroll
        for (int k = 0; k < 32; k++) {
            float4 a  = *reinterpret_cast<const float4*>(&As[k][ty * 4]);
            float4 b1v = *reinterpret_cast<const float4*>(&B1s[k][tx * 4]);
            float4 b2v = *reinterpret_cast<const float4*>(&B2s[k][tx * 4]);
            float av[4] = {a.x, a.y, a.z, a.w};
            float bv1[4] = {b1v.x, b1v.y, b1v.z, b1v.w};
            float bv2[4] = {b2v.x, b2v.y, b2v.z, b2v.w};
#pragma unroll
            for (int i = 0; i < 4; i++)
#pragma unroll
                for (int j = 0; j < 4; j++) {
                    acc1[i][j] = fmaf(av[i], bv1[j], acc1[i][j]);
                    acc2[i][j] = fmaf(av[i], bv2[j], acc2[i][j]);
                }
        }
        __syncthreads();
    }

    float bg[4], bb[4];
#pragma unroll
    for (int j = 0; j < 4; j++) {
        bg[j] = b2[c0 + tx * 4 + j];
        bb[j] = b2[256 + c0 + tx * 4 + j];
    }
#pragma unroll
    for (int i = 0; i < 4; i++) {
        int m = m0 + ty * 4 + i;
        float gate = tanhf(g_rowsum[m]);
        float4 nd = *reinterpret_cast<const float4*>(&nodes[(size_t)m * DDIM + c0 + tx * 4]);
        float ndv[4] = {nd.x, nd.y, nd.z, nd.w};
        float4 o;
        float ov[4];
#pragma unroll
        for (int j = 0; j < 4; j++) {
            float gamma = acc1[i][j] + bg[j];
            float beta  = acc2[i][j] + bb[j];
            float film  = fmaf(1.0f + gamma, ndv[j], beta);
            ov[j] = fmaf(film, gate, ndv[j]);
        }
        o.x = ov[0]; o.y = ov[1]; o.z = ov[2]; o.w = ov[3];
        *reinterpret_cast<float4*>(&out[(size_t)m * DDIM + c0 + tx * 4]) = o;
    }
}

// ---------------- host launcher ----------------
extern "C" void kernel_launch(void* const* d_in, const int* in_sizes, int n_in,
                              void* d_out, int out_size) {
    const float* nodes = (const float*)d_in[0];
    const int*   pat   = (const int*)d_in[1];
    const float* thr   = (const float*)d_in[2];
    const float* tmp   = (const float*)d_in[3];
    const float* W1    = (const float*)d_in[4];
    const float* b1    = (const float*)d_in[5];
    const float* W2    = (const float*)d_in[6];
    const float* b2    = (const float*)d_in[7];
    float* out = (float*)d_out;

    (void)cudaFuncSetAttribute(k_fused, cudaFuncAttributeMaxDynamicSharedMemorySize,
                               SM_TOTAL_BYTES);

    k_rnorm<<<BTOT / 8, 256>>>(nodes);
    k_fused<<<BTOT / MTILE, 256, SM_TOTAL_BYTES>>>(nodes, pat, thr, tmp);
    dim3 g2(BTOT / 64, DDIM / 64);
    k_mlp1<<<g2, 256>>>(W1, b1);
    k_mlp2<<<g2, 256>>>(W2, b2, nodes, out);
}